// round 2
// baseline (speedup 1.0000x reference)
#include <cuda_runtime.h>
#include <cstdint>

// Problem constants
#define NN 50000
#define CC 128
#define EE 600000

// Scratch (device globals; no cudaMalloc allowed)
__device__ float g_agg[NN * CC];
__device__ float g_cnt[NN];
__device__ float g_inv[NN];
__device__ float g_x1[NN * CC];
__device__ float g_x2[NN * CC];

// ---------------------------------------------------------------------------
// zero (float4-wide)
__global__ void zero4_kernel(float4* p, int n4) {
    int i = blockIdx.x * blockDim.x + threadIdx.x;
    int stride = gridDim.x * blockDim.x;
    float4 z = make_float4(0.f, 0.f, 0.f, 0.f);
    for (; i < n4; i += stride) p[i] = z;
}

// ---------------------------------------------------------------------------
// in-degree counts (as float). edge_index is int32: ei[0:E)=src, ei[E:2E)=dst
__global__ void count_kernel(const int* __restrict__ ei, float* __restrict__ cnt, int E) {
    int i = blockIdx.x * blockDim.x + threadIdx.x;
    int stride = gridDim.x * blockDim.x;
    for (; i < E; i += stride) {
        int d = ei[E + i];
        atomicAdd(&cnt[d], 1.0f);
    }
}

__global__ void inv_kernel(const float* __restrict__ cnt, float* __restrict__ inv, int n) {
    int i = blockIdx.x * blockDim.x + threadIdx.x;
    if (i < n) inv[i] = 1.0f / fmaxf(cnt[i], 1.0f);
}

// ---------------------------------------------------------------------------
// scatter: one warp per edge; lane handles 4 consecutive floats (float4 gather,
// 4 scalar atomic adds -> REDG). x rows are 512B, L2-resident.
__global__ void scatter_kernel(const float* __restrict__ x,
                               const int* __restrict__ ei,
                               float* __restrict__ agg, int E) {
    int gwarp = (blockIdx.x * blockDim.x + threadIdx.x) >> 5;
    int lane = threadIdx.x & 31;
    int nwarps = (gridDim.x * blockDim.x) >> 5;
    for (int e = gwarp; e < E; e += nwarps) {
        int s = ei[e];
        int d = ei[E + e];
        float4 v = ((const float4*)(x + (size_t)s * CC))[lane];
        float* dp = agg + (size_t)d * CC + lane * 4;
        atomicAdd(dp + 0, v.x);
        atomicAdd(dp + 1, v.y);
        atomicAdd(dp + 2, v.z);
        atomicAdd(dp + 3, v.w);
    }
}

// ---------------------------------------------------------------------------
// Fused GEMM: out[M,128] = relu?( [scale(A0) | A1] (M x 256) @ [[W0];[W1]] (256 x 128) + bias )
//   - A0 scaled per-row by inv[] when inv != nullptr (mean aggregation)
//   - W0 covers k in [0,128), W1 covers k in [128,256); both 128x128 row-major
// Block tile: 64 (M) x 128 (N), K chunks of 32. 256 threads, 4x8 per thread.
__global__ __launch_bounds__(256) void gemm_kernel(
    const float* __restrict__ A0, const float* __restrict__ A1,
    const float* __restrict__ inv,
    const float* __restrict__ W0, const float* __restrict__ W1,
    const float* __restrict__ bias,
    float* __restrict__ out, int M, int do_relu) {

    __shared__ float As[32][65];    // [k][m], padded
    __shared__ float Bs[32][128];   // [k][n]

    const int tid = threadIdx.x;
    const int tx = tid & 15;        // N direction: 16 threads x 8 cols
    const int ty = tid >> 4;        // M direction: 16 threads x 4 rows
    const int row0 = blockIdx.x * 64;

    float acc[4][8];
#pragma unroll
    for (int r = 0; r < 4; r++)
#pragma unroll
        for (int c = 0; c < 8; c++) acc[r][c] = 0.f;

    for (int kc = 0; kc < 256; kc += 32) {
        const float* SA = (kc < 128) ? A0 : A1;
        const float* SW = (kc < 128) ? W0 : W1;
        const int koff = kc & 127;
        const bool doScale = (kc < 128) && (inv != nullptr);

        // Load A tile (64 x 32), transposed into As[k][m]. 512 float4 -> 2/thread.
#pragma unroll
        for (int i = 0; i < 2; i++) {
            int idx = tid + i * 256;     // 0..511
            int m = idx >> 3;
            int k4 = idx & 7;
            int row = row0 + m;
            float4 v = make_float4(0.f, 0.f, 0.f, 0.f);
            float s = 1.f;
            if (row < M) {
                v = *(const float4*)(SA + (size_t)row * CC + koff + k4 * 4);
                if (doScale) s = inv[row];
            }
            As[k4 * 4 + 0][m] = v.x * s;
            As[k4 * 4 + 1][m] = v.y * s;
            As[k4 * 4 + 2][m] = v.z * s;
            As[k4 * 4 + 3][m] = v.w * s;
        }

        // Load B tile (32 x 128). 1024 float4 -> 4/thread.
#pragma unroll
        for (int i = 0; i < 4; i++) {
            int idx = tid + i * 256;     // 0..1023
            int kr = idx >> 5;
            int c4 = idx & 31;
            float4 v = *(const float4*)(SW + (size_t)(koff + kr) * CC + c4 * 4);
            *(float4*)(&Bs[kr][c4 * 4]) = v;
        }
        __syncthreads();

#pragma unroll
        for (int k = 0; k < 32; k++) {
            float a[4], b[8];
#pragma unroll
            for (int r = 0; r < 4; r++) a[r] = As[k][ty * 4 + r];
#pragma unroll
            for (int c = 0; c < 8; c++) b[c] = Bs[k][tx * 8 + c];
#pragma unroll
            for (int r = 0; r < 4; r++)
#pragma unroll
                for (int c = 0; c < 8; c++) acc[r][c] = fmaf(a[r], b[c], acc[r][c]);
        }
        __syncthreads();
    }

    // Epilogue: bias + optional relu, float4 stores
    float bv[8];
#pragma unroll
    for (int c = 0; c < 8; c++) bv[c] = bias[tx * 8 + c];

#pragma unroll
    for (int r = 0; r < 4; r++) {
        int row = row0 + ty * 4 + r;
        if (row >= M) break;
        float v0 = acc[r][0] + bv[0], v1 = acc[r][1] + bv[1];
        float v2 = acc[r][2] + bv[2], v3 = acc[r][3] + bv[3];
        float v4 = acc[r][4] + bv[4], v5 = acc[r][5] + bv[5];
        float v6 = acc[r][6] + bv[6], v7 = acc[r][7] + bv[7];
        if (do_relu) {
            v0 = fmaxf(v0, 0.f); v1 = fmaxf(v1, 0.f); v2 = fmaxf(v2, 0.f); v3 = fmaxf(v3, 0.f);
            v4 = fmaxf(v4, 0.f); v5 = fmaxf(v5, 0.f); v6 = fmaxf(v6, 0.f); v7 = fmaxf(v7, 0.f);
        }
        float* op = out + (size_t)row * CC + tx * 8;
        *(float4*)(op + 0) = make_float4(v0, v1, v2, v3);
        *(float4*)(op + 4) = make_float4(v4, v5, v6, v7);
    }
}

// ---------------------------------------------------------------------------
extern "C" void kernel_launch(void* const* d_in, const int* in_sizes, int n_in,
                              void* d_out, int out_size) {
    const float* x     = (const float*)d_in[0];
    const int*   ei    = (const int*)d_in[1];     // int32 (JAX canonicalizes int64->int32)
    const float* W1_l  = (const float*)d_in[2];
    const float* b1_l  = (const float*)d_in[3];
    const float* W1_r  = (const float*)d_in[4];
    const float* W2_l  = (const float*)d_in[5];
    const float* b2_l  = (const float*)d_in[6];
    const float* W2_r  = (const float*)d_in[7];
    const float* W_lin = (const float*)d_in[8];
    const float* b_lin = (const float*)d_in[9];
    float* out = (float*)d_out;

    const int M = in_sizes[0] / CC;      // 50000
    const int E = in_sizes[1] / 2;       // 600000

    // Resolve scratch addresses (query only, graph-capture safe)
    float *agg, *cnt, *inv, *x1, *x2;
    cudaGetSymbolAddress((void**)&agg, g_agg);
    cudaGetSymbolAddress((void**)&cnt, g_cnt);
    cudaGetSymbolAddress((void**)&inv, g_inv);
    cudaGetSymbolAddress((void**)&x1, g_x1);
    cudaGetSymbolAddress((void**)&x2, g_x2);

    const int TB = 256;
    const int aggN4 = (M * CC) / 4;
    const int cntN4 = (M + 3) / 4;
    const int scatterBlocks = (E * 32 + TB - 1) / TB;
    const int gemmBlocks = (M + 63) / 64;

    // --- counts (shared by both layers) ---
    zero4_kernel<<<256, TB>>>((float4*)cnt, cntN4);
    count_kernel<<<512, TB>>>(ei, cnt, E);
    inv_kernel<<<(M + TB - 1) / TB, TB>>>(cnt, inv, M);

    // --- layer 1 ---
    zero4_kernel<<<1024, TB>>>((float4*)agg, aggN4);
    scatter_kernel<<<scatterBlocks, TB>>>(x, ei, agg, E);
    gemm_kernel<<<gemmBlocks, TB>>>(agg, x, inv, W1_l, W1_r, b1_l, x1, M, 1);

    // --- layer 2 ---
    zero4_kernel<<<1024, TB>>>((float4*)agg, aggN4);
    scatter_kernel<<<scatterBlocks, TB>>>(x1, ei, agg, E);
    gemm_kernel<<<gemmBlocks, TB>>>(agg, x1, inv, W2_l, W2_r, b2_l, x2, M, 1);

    // --- final linear: [x1 | x2] @ W_lin + b_lin (no relu) ---
    gemm_kernel<<<gemmBlocks, TB>>>(x1, x2, nullptr, W_lin, W_lin + 128 * 128, b_lin, out, M, 0);
}

// round 4
// speedup vs baseline: 1.5364x; 1.5364x over previous
#include <cuda_runtime.h>
#include <cuda_bf16.h>
#include <cstdint>

#define NN 50000
#define CC 128

// Scratch (device globals; no cudaMalloc allowed)
__device__ float g_agg[NN * CC];
__device__ float g_cnt[NN];
__device__ float g_inv[NN];
__device__ float g_x1[NN * CC];
__device__ float g_x2[NN * CC];
// Pre-transposed bf16 hi/lo weights: [gemm(3)][n(128)][k(256)]
__device__ __nv_bfloat16 g_wbh[3 * 128 * 256];
__device__ __nv_bfloat16 g_wbl[3 * 128 * 256];

// ---------------------------------------------------------------------------
__device__ __forceinline__ uint32_t smem_u32(const void* p) {
    uint32_t a;
    asm("{ .reg .u64 t; cvta.to.shared.u64 t, %1; cvt.u32.u64 %0, t; }" : "=r"(a) : "l"(p));
    return a;
}
__device__ __forceinline__ void ldsm_x4(uint32_t& r0, uint32_t& r1, uint32_t& r2, uint32_t& r3,
                                        uint32_t addr) {
    asm volatile("ldmatrix.sync.aligned.m8n8.x4.shared.b16 {%0,%1,%2,%3}, [%4];"
                 : "=r"(r0), "=r"(r1), "=r"(r2), "=r"(r3) : "r"(addr));
}
__device__ __forceinline__ void mma_bf16(float* d, const uint32_t* a, uint32_t b0, uint32_t b1) {
    asm volatile(
        "mma.sync.aligned.m16n8k16.row.col.f32.bf16.bf16.f32 "
        "{%0,%1,%2,%3}, {%4,%5,%6,%7}, {%8,%9}, {%0,%1,%2,%3};"
        : "+f"(d[0]), "+f"(d[1]), "+f"(d[2]), "+f"(d[3])
        : "r"(a[0]), "r"(a[1]), "r"(a[2]), "r"(a[3]), "r"(b0), "r"(b1));
}

// ---------------------------------------------------------------------------
__global__ void zero4_kernel(float4* p, int n4) {
    int i = blockIdx.x * blockDim.x + threadIdx.x;
    int stride = gridDim.x * blockDim.x;
    float4 z = make_float4(0.f, 0.f, 0.f, 0.f);
    for (; i < n4; i += stride) p[i] = z;
}

__global__ void count_kernel(const int* __restrict__ ei, float* __restrict__ cnt, int E) {
    int i = blockIdx.x * blockDim.x + threadIdx.x;
    int stride = gridDim.x * blockDim.x;
    for (; i < E; i += stride) atomicAdd(&cnt[ei[E + i]], 1.0f);
}

__global__ void inv_kernel(const float* __restrict__ cnt, float* __restrict__ inv, int n) {
    int i = blockIdx.x * blockDim.x + threadIdx.x;
    if (i < n) inv[i] = 1.0f / fmaxf(cnt[i], 1.0f);
}

// scatter: one warp per edge; lane handles 4 consecutive floats
__global__ void scatter_kernel(const float* __restrict__ x,
                               const int* __restrict__ ei,
                               float* __restrict__ agg, int E) {
    int gwarp = (blockIdx.x * blockDim.x + threadIdx.x) >> 5;
    int lane = threadIdx.x & 31;
    int nwarps = (gridDim.x * blockDim.x) >> 5;
    for (int e = gwarp; e < E; e += nwarps) {
        int s = ei[e];
        int d = ei[E + e];
        float4 v = ((const float4*)(x + (size_t)s * CC))[lane];
        float* dp = agg + (size_t)d * CC + lane * 4;
        atomicAdd(dp + 0, v.x);
        atomicAdd(dp + 1, v.y);
        atomicAdd(dp + 2, v.z);
        atomicAdd(dp + 3, v.w);
    }
}

// ---------------------------------------------------------------------------
// Weight prep: W[k][n] (row-major, 2x 128x128 stacked in k) -> Wt[n][k] bf16 hi/lo
__global__ void prep_w_kernel(const float* w0l, const float* w0r,
                              const float* w1l, const float* w1r,
                              const float* w2l, const float* w2r,
                              __nv_bfloat16* wh, __nv_bfloat16* wl) {
    int gid = blockIdx.x * blockDim.x + threadIdx.x;   // [g][n][k]
    if (gid >= 3 * 128 * 256) return;
    int g = gid >> 15;
    int rem = gid & 32767;
    int n = rem >> 8;
    int k = rem & 255;
    const float* W;
    if (g == 0)      W = (k < 128) ? w0l : w0r;
    else if (g == 1) W = (k < 128) ? w1l : w1r;
    else             W = (k < 128) ? w2l : w2r;
    float v = W[(size_t)(k & 127) * CC + n];
    __nv_bfloat16 h = __float2bfloat16(v);
    __nv_bfloat16 l = __float2bfloat16(v - __bfloat162float(h));
    wh[gid] = h;
    wl[gid] = l;
}

// ---------------------------------------------------------------------------
// bf16x3 tensor-core GEMM via mma.sync:
// out[M,128] = act( [scale(A0) | A1] (Mx256) @ Wt^T + bias )
// CTA tile 128x128, 8 warps (4M x 2N), warp tile 32x64, K chunks of 32.
// SMEM rows padded to 80B -> conflict-free ldmatrix without swizzle.
#define ROW_B 80

__global__ __launch_bounds__(256, 2) void gemm_mma_kernel(
    const float* __restrict__ A0, const float* __restrict__ A1,
    const float* __restrict__ inv,
    const __nv_bfloat16* __restrict__ wh, const __nv_bfloat16* __restrict__ wl,
    const float* __restrict__ bias,
    float* __restrict__ out, int M, int do_relu) {

    __shared__ __align__(16) char sA_hi[128 * ROW_B];
    __shared__ __align__(16) char sA_lo[128 * ROW_B];
    __shared__ __align__(16) char sB_hi[128 * ROW_B];
    __shared__ __align__(16) char sB_lo[128 * ROW_B];

    const int tid = threadIdx.x;
    const int lane = tid & 31;
    const int wid = tid >> 5;
    const int wm = (wid & 3) * 32;       // warp M offset in tile
    const int wn = (wid >> 2) * 64;      // warp N offset
    const int row0 = blockIdx.x * 128;

    float acc[2][8][4] = {};

    const uint32_t aHi = smem_u32(sA_hi), aLo = smem_u32(sA_lo);
    const uint32_t bHi = smem_u32(sB_hi), bLo = smem_u32(sB_lo);

    // ldmatrix lane->address components
    const int a_mrow = ((lane >> 3) & 1) * 8 + (lane & 7);  // + (matrix&1)*8
    const int a_j = lane >> 4;                               // matrix>>1
    const int b_nrow = (lane >> 4) * 8 + (lane & 7);         // + (matrix>>1)*8
    const int b_j = (lane >> 3) & 1;                         // matrix&1

    for (int c = 0; c < 8; c++) {
        const float* SA = (c < 4) ? A0 : A1;
        const int koff = (c & 3) * 32;
        const bool doScale = (inv != nullptr) && (c < 4);

        // A chunk: 128 rows x 32 fp32 -> bf16 hi/lo (with mean scaling)
#pragma unroll
        for (int i = 0; i < 4; i++) {
            int idx = tid + (i << 8);        // 0..1023
            int m = idx >> 3, k4 = idx & 7;
            int row = row0 + m;
            float4 v = make_float4(0.f, 0.f, 0.f, 0.f);
            float s = 1.f;
            if (row < M) {
                v = *(const float4*)(SA + (size_t)row * CC + koff + (k4 << 2));
                if (doScale) s = __ldg(inv + row);
            }
            v.x *= s; v.y *= s; v.z *= s; v.w *= s;
            __nv_bfloat162 h01 = make_bfloat162(__float2bfloat16(v.x), __float2bfloat16(v.y));
            __nv_bfloat162 h23 = make_bfloat162(__float2bfloat16(v.z), __float2bfloat16(v.w));
            __nv_bfloat162 l01 = make_bfloat162(
                __float2bfloat16(v.x - __bfloat162float(h01.x)),
                __float2bfloat16(v.y - __bfloat162float(h01.y)));
            __nv_bfloat162 l23 = make_bfloat162(
                __float2bfloat16(v.z - __bfloat162float(h23.x)),
                __float2bfloat16(v.w - __bfloat162float(h23.y)));
            char* pd = sA_hi + m * ROW_B + (k4 << 3);
            *(__nv_bfloat162*)(pd + 0) = h01;
            *(__nv_bfloat162*)(pd + 4) = h23;
            char* pl = sA_lo + m * ROW_B + (k4 << 3);
            *(__nv_bfloat162*)(pl + 0) = l01;
            *(__nv_bfloat162*)(pl + 4) = l23;
        }
        // B chunk: copy 128 rows x 64B from prepped [n][k] bf16 images
#pragma unroll
        for (int i = 0; i < 2; i++) {
            int idx = tid + (i << 8);        // 0..511
            int n = idx >> 2, j = idx & 3;
            size_t srcOff = (size_t)n * 512 + (size_t)c * 64 + (size_t)j * 16;
            uint4 vh = *(const uint4*)((const char*)wh + srcOff);
            uint4 vlo = *(const uint4*)((const char*)wl + srcOff);
            *(uint4*)(sB_hi + n * ROW_B + (j << 4)) = vh;
            *(uint4*)(sB_lo + n * ROW_B + (j << 4)) = vlo;
        }
        __syncthreads();

#pragma unroll
        for (int ks = 0; ks < 2; ks++) {
            uint32_t ah[8], al[8];
#pragma unroll
            for (int mi = 0; mi < 2; mi++) {
                uint32_t off = (uint32_t)((wm + mi * 16 + a_mrow) * ROW_B + ks * 32 + a_j * 16);
                ldsm_x4(ah[mi * 4 + 0], ah[mi * 4 + 1], ah[mi * 4 + 2], ah[mi * 4 + 3], aHi + off);
                ldsm_x4(al[mi * 4 + 0], al[mi * 4 + 1], al[mi * 4 + 2], al[mi * 4 + 3], aLo + off);
            }
#pragma unroll
            for (int bg = 0; bg < 4; bg++) {
                uint32_t off = (uint32_t)((wn + bg * 16 + b_nrow) * ROW_B + ks * 32 + b_j * 16);
                uint32_t bh0, bh1, bh2, bh3, bl0, bl1, bl2, bl3;
                ldsm_x4(bh0, bh1, bh2, bh3, bHi + off);
                ldsm_x4(bl0, bl1, bl2, bl3, bLo + off);
#pragma unroll
                for (int mi = 0; mi < 2; mi++) {
                    mma_bf16(acc[mi][bg * 2 + 0], ah + mi * 4, bh0, bh1);
                    mma_bf16(acc[mi][bg * 2 + 0], ah + mi * 4, bl0, bl1);
                    mma_bf16(acc[mi][bg * 2 + 0], al + mi * 4, bh0, bh1);
                    mma_bf16(acc[mi][bg * 2 + 1], ah + mi * 4, bh2, bh3);
                    mma_bf16(acc[mi][bg * 2 + 1], ah + mi * 4, bl2, bl3);
                    mma_bf16(acc[mi][bg * 2 + 1], al + mi * 4, bh2, bh3);
                }
            }
        }
        __syncthreads();
    }

    // epilogue: d0,d1 -> row g, cols c,c+1 ; d2,d3 -> row g+8
    const int rbase = row0 + wm + (lane >> 2);
    const int cbase = wn + (lane & 3) * 2;
#pragma unroll
    for (int mi = 0; mi < 2; mi++) {
#pragma unroll
        for (int ni = 0; ni < 8; ni++) {
            int col = cbase + ni * 8;
            float b0 = __ldg(bias + col), b1 = __ldg(bias + col + 1);
            int r1 = rbase + mi * 16, r2 = r1 + 8;
            float v0 = acc[mi][ni][0] + b0, v1 = acc[mi][ni][1] + b1;
            float v2 = acc[mi][ni][2] + b0, v3 = acc[mi][ni][3] + b1;
            if (do_relu) {
                v0 = fmaxf(v0, 0.f); v1 = fmaxf(v1, 0.f);
                v2 = fmaxf(v2, 0.f); v3 = fmaxf(v3, 0.f);
            }
            if (r1 < M) *(float2*)(out + (size_t)r1 * CC + col) = make_float2(v0, v1);
            if (r2 < M) *(float2*)(out + (size_t)r2 * CC + col) = make_float2(v2, v3);
        }
    }
}

// ---------------------------------------------------------------------------
extern "C" void kernel_launch(void* const* d_in, const int* in_sizes, int n_in,
                              void* d_out, int out_size) {
    const float* x     = (const float*)d_in[0];
    const int*   ei    = (const int*)d_in[1];     // int32 (JAX canonicalizes int64->int32)
    const float* W1_l  = (const float*)d_in[2];
    const float* b1_l  = (const float*)d_in[3];
    const float* W1_r  = (const float*)d_in[4];
    const float* W2_l  = (const float*)d_in[5];
    const float* b2_l  = (const float*)d_in[6];
    const float* W2_r  = (const float*)d_in[7];
    const float* W_lin = (const float*)d_in[8];
    const float* b_lin = (const float*)d_in[9];
    float* out = (float*)d_out;

    const int M = in_sizes[0] / CC;      // 50000
    const int E = in_sizes[1] / 2;       // 600000

    float *agg, *cnt, *inv, *x1, *x2;
    __nv_bfloat16 *wbh, *wbl;
    cudaGetSymbolAddress((void**)&agg, g_agg);
    cudaGetSymbolAddress((void**)&cnt, g_cnt);
    cudaGetSymbolAddress((void**)&inv, g_inv);
    cudaGetSymbolAddress((void**)&x1, g_x1);
    cudaGetSymbolAddress((void**)&x2, g_x2);
    cudaGetSymbolAddress((void**)&wbh, g_wbh);
    cudaGetSymbolAddress((void**)&wbl, g_wbl);

    const int TB = 256;
    const int aggN4 = (M * CC) / 4;
    const int cntN4 = (M + 3) / 4;
    const int scatterBlocks = (E * 32 + TB - 1) / TB;
    const int gemmBlocks = (M + 127) / 128;

    // weight prep (replayed every graph launch; deterministic)
    prep_w_kernel<<<384, TB>>>(W1_l, W1_r, W2_l, W2_r, W_lin, W_lin + 128 * CC, wbh, wbl);

    // counts
    zero4_kernel<<<256, TB>>>((float4*)cnt, cntN4);
    count_kernel<<<512, TB>>>(ei, cnt, E);
    inv_kernel<<<(M + TB - 1) / TB, TB>>>(cnt, inv, M);

    // layer 1
    zero4_kernel<<<1024, TB>>>((float4*)agg, aggN4);
    scatter_kernel<<<scatterBlocks, TB>>>(x, ei, agg, E);
    gemm_mma_kernel<<<gemmBlocks, TB>>>(agg, x, inv, wbh, wbl, b1_l, x1, M, 1);

    // layer 2
    zero4_kernel<<<1024, TB>>>((float4*)agg, aggN4);
    scatter_kernel<<<scatterBlocks, TB>>>(x1, ei, agg, E);
    gemm_mma_kernel<<<gemmBlocks, TB>>>(agg, x1, inv,
                                        wbh + 32768, wbl + 32768, b2_l, x2, M, 1);

    // final linear: [x1 | x2] @ W_lin + b_lin (no relu)
    gemm_mma_kernel<<<gemmBlocks, TB>>>(x1, x2, nullptr,
                                        wbh + 65536, wbl + 65536, b_lin, out, M, 0);
}

// round 5
// speedup vs baseline: 2.9961x; 1.9501x over previous
#include <cuda_runtime.h>
#include <cuda_bf16.h>
#include <cstdint>

#define NN 50000
#define CC 128

// Scratch (device globals; no cudaMalloc allowed)
__device__ float g_agg[NN * CC];
__device__ float g_cnt[NN];
__device__ float g_x1[NN * CC];
__device__ float g_x2[NN * CC];
// Pre-transposed bf16 hi/lo weights: [gemm(3)][n(128)][k(256)]
__device__ __nv_bfloat16 g_wbh[3 * 128 * 256];
__device__ __nv_bfloat16 g_wbl[3 * 128 * 256];

// ---------------------------------------------------------------------------
__device__ __forceinline__ uint32_t smem_u32(const void* p) {
    uint32_t a;
    asm("{ .reg .u64 t; cvta.to.shared.u64 t, %1; cvt.u32.u64 %0, t; }" : "=r"(a) : "l"(p));
    return a;
}
__device__ __forceinline__ void ldsm_x4(uint32_t& r0, uint32_t& r1, uint32_t& r2, uint32_t& r3,
                                        uint32_t addr) {
    asm volatile("ldmatrix.sync.aligned.m8n8.x4.shared.b16 {%0,%1,%2,%3}, [%4];"
                 : "=r"(r0), "=r"(r1), "=r"(r2), "=r"(r3) : "r"(addr));
}
__device__ __forceinline__ void mma_bf16(float* d, const uint32_t* a, uint32_t b0, uint32_t b1) {
    asm volatile(
        "mma.sync.aligned.m16n8k16.row.col.f32.bf16.bf16.f32 "
        "{%0,%1,%2,%3}, {%4,%5,%6,%7}, {%8,%9}, {%0,%1,%2,%3};"
        : "+f"(d[0]), "+f"(d[1]), "+f"(d[2]), "+f"(d[3])
        : "r"(a[0]), "r"(a[1]), "r"(a[2]), "r"(a[3]), "r"(b0), "r"(b1));
}
__device__ __forceinline__ void cp_async16(uint32_t dst, const void* src) {
    asm volatile("cp.async.cg.shared.global [%0], [%1], 16;" :: "r"(dst), "l"(src) : "memory");
}

// ---------------------------------------------------------------------------
// scatter: warp processes batches of 32 edges (coalesced index loads + shuffle).
// One red.global.add.v4.f32 per lane per edge. Optionally accumulates in-degree.
__global__ void scatter_kernel(const float* __restrict__ x,
                               const int* __restrict__ ei,
                               float* __restrict__ agg,
                               float* __restrict__ cnt, int E) {
    const int lane = threadIdx.x & 31;
    const int gwarp = (blockIdx.x * blockDim.x + threadIdx.x) >> 5;
    const int nwarps = (gridDim.x * blockDim.x) >> 5;
    for (int base = gwarp * 32; base < E; base += nwarps * 32) {
        int rem = E - base;
        int nb = rem < 32 ? rem : 32;
        int s = 0, d = 0;
        if (lane < nb) {
            s = ei[base + lane];
            d = ei[E + base + lane];
            if (cnt) atomicAdd(&cnt[d], 1.0f);
        }
#pragma unroll 4
        for (int i = 0; i < nb; i++) {
            int si = __shfl_sync(0xffffffffu, s, i);
            int di = __shfl_sync(0xffffffffu, d, i);
            float4 v = __ldg((const float4*)(x + (size_t)si * CC) + lane);
            float* dp = agg + (size_t)di * CC + lane * 4;
            asm volatile("red.global.add.v4.f32 [%0], {%1,%2,%3,%4};"
                         :: "l"(dp), "f"(v.x), "f"(v.y), "f"(v.z), "f"(v.w) : "memory");
        }
    }
}

// ---------------------------------------------------------------------------
// Weight prep: W[k][n] (row-major, 2x 128x128 stacked in k) -> Wt[n][k] bf16 hi/lo
__global__ void prep_w_kernel(const float* w0l, const float* w0r,
                              const float* w1l, const float* w1r,
                              const float* w2l, const float* w2r,
                              __nv_bfloat16* wh, __nv_bfloat16* wl) {
    int gid = blockIdx.x * blockDim.x + threadIdx.x;   // [g][n][k]
    if (gid >= 3 * 128 * 256) return;
    int g = gid >> 15;
    int rem = gid & 32767;
    int n = rem >> 8;
    int k = rem & 255;
    const float* W;
    if (g == 0)      W = (k < 128) ? w0l : w0r;
    else if (g == 1) W = (k < 128) ? w1l : w1r;
    else             W = (k < 128) ? w2l : w2r;
    float v = W[(size_t)(k & 127) * CC + n];
    __nv_bfloat16 h = __float2bfloat16(v);
    __nv_bfloat16 l = __float2bfloat16(v - __bfloat162float(h));
    wh[gid] = h;
    wl[gid] = l;
}

// ---------------------------------------------------------------------------
// bf16x3 tensor-core GEMM via mma.sync, software-pipelined:
//   A chunk (c+1) prefetched into registers during MMA of chunk c
//   B chunk loaded via cp.async (prepped bf16, no conversion)
// out[M,128] = act( [scale(A0) | A1] (Mx256) @ Wt^T + bias )
// scale = 1/max(cnt,1) applied to A0 rows when cnt != nullptr.
#define ROW_B 80

__global__ __launch_bounds__(256, 2) void gemm_mma_kernel(
    const float* __restrict__ A0, const float* __restrict__ A1,
    const float* __restrict__ cnt,
    const __nv_bfloat16* __restrict__ wh, const __nv_bfloat16* __restrict__ wl,
    const float* __restrict__ bias,
    float* __restrict__ out, int M, int do_relu) {

    __shared__ __align__(16) char sA_hi[128 * ROW_B];
    __shared__ __align__(16) char sA_lo[128 * ROW_B];
    __shared__ __align__(16) char sB_hi[128 * ROW_B];
    __shared__ __align__(16) char sB_lo[128 * ROW_B];

    const int tid = threadIdx.x;
    const int lane = tid & 31;
    const int wid = tid >> 5;
    const int wm = (wid & 3) * 32;       // warp M offset
    const int wn = (wid >> 2) * 64;      // warp N offset
    const int row0 = blockIdx.x * 128;

    float acc[2][8][4] = {};

    const uint32_t aHi = smem_u32(sA_hi), aLo = smem_u32(sA_lo);
    const uint32_t bHi = smem_u32(sB_hi), bLo = smem_u32(sB_lo);

    const int a_mrow = ((lane >> 3) & 1) * 8 + (lane & 7);
    const int a_j = lane >> 4;
    const int b_nrow = (lane >> 4) * 8 + (lane & 7);
    const int b_j = (lane >> 3) & 1;

    // A prefetch registers (4 float4 rows/thread + per-row scale)
    float4 vA[4];
    float sc[4];

    auto loadA = [&](int c) {
        const float* SA = (c < 4) ? A0 : A1;
        const int koff = (c & 3) * 32;
        const bool doScale = (cnt != nullptr) && (c < 4);
#pragma unroll
        for (int i = 0; i < 4; i++) {
            int idx = tid + (i << 8);
            int m = idx >> 3, k4 = idx & 7;
            int row = row0 + m;
            if (row < M) {
                vA[i] = *(const float4*)(SA + (size_t)row * CC + koff + (k4 << 2));
                sc[i] = doScale ? (1.0f / fmaxf(__ldg(cnt + row), 1.0f)) : 1.0f;
            } else {
                vA[i] = make_float4(0.f, 0.f, 0.f, 0.f);
                sc[i] = 1.0f;
            }
        }
    };

    loadA(0);

    for (int c = 0; c < 8; c++) {
        // B chunk via cp.async (16B per op, 4 per thread)
#pragma unroll
        for (int i = 0; i < 2; i++) {
            int idx = tid + (i << 8);        // 0..511
            int n = idx >> 2, j = idx & 3;
            size_t srcOff = (size_t)n * 512 + (size_t)c * 64 + (size_t)j * 16;
            cp_async16(bHi + n * ROW_B + (j << 4), (const char*)wh + srcOff);
            cp_async16(bLo + n * ROW_B + (j << 4), (const char*)wl + srcOff);
        }
        asm volatile("cp.async.commit_group;" ::: "memory");

        // A chunk: split prefetched fp32 into bf16 hi/lo, STS
#pragma unroll
        for (int i = 0; i < 4; i++) {
            int idx = tid + (i << 8);
            int m = idx >> 3, k4 = idx & 7;
            float s = sc[i];
            float x0 = vA[i].x * s, x1 = vA[i].y * s, x2 = vA[i].z * s, x3 = vA[i].w * s;
            __nv_bfloat162 h01 = make_bfloat162(__float2bfloat16(x0), __float2bfloat16(x1));
            __nv_bfloat162 h23 = make_bfloat162(__float2bfloat16(x2), __float2bfloat16(x3));
            __nv_bfloat162 l01 = make_bfloat162(
                __float2bfloat16(x0 - __bfloat162float(h01.x)),
                __float2bfloat16(x1 - __bfloat162float(h01.y)));
            __nv_bfloat162 l23 = make_bfloat162(
                __float2bfloat16(x2 - __bfloat162float(h23.x)),
                __float2bfloat16(x3 - __bfloat162float(h23.y)));
            char* pd = sA_hi + m * ROW_B + (k4 << 3);
            *(__nv_bfloat162*)(pd + 0) = h01;
            *(__nv_bfloat162*)(pd + 4) = h23;
            char* pl = sA_lo + m * ROW_B + (k4 << 3);
            *(__nv_bfloat162*)(pl + 0) = l01;
            *(__nv_bfloat162*)(pl + 4) = l23;
        }

        // issue next chunk's A loads early (hidden under MMA section)
        if (c < 7) loadA(c + 1);

        asm volatile("cp.async.wait_group 0;" ::: "memory");
        __syncthreads();

#pragma unroll
        for (int ks = 0; ks < 2; ks++) {
            uint32_t ah[8], al[8];
#pragma unroll
            for (int mi = 0; mi < 2; mi++) {
                uint32_t off = (uint32_t)((wm + mi * 16 + a_mrow) * ROW_B + ks * 32 + a_j * 16);
                ldsm_x4(ah[mi * 4 + 0], ah[mi * 4 + 1], ah[mi * 4 + 2], ah[mi * 4 + 3], aHi + off);
                ldsm_x4(al[mi * 4 + 0], al[mi * 4 + 1], al[mi * 4 + 2], al[mi * 4 + 3], aLo + off);
            }
#pragma unroll
            for (int bg = 0; bg < 4; bg++) {
                uint32_t off = (uint32_t)((wn + bg * 16 + b_nrow) * ROW_B + ks * 32 + b_j * 16);
                uint32_t bh0, bh1, bh2, bh3, bl0, bl1, bl2, bl3;
                ldsm_x4(bh0, bh1, bh2, bh3, bHi + off);
                ldsm_x4(bl0, bl1, bl2, bl3, bLo + off);
#pragma unroll
                for (int mi = 0; mi < 2; mi++) {
                    mma_bf16(acc[mi][bg * 2 + 0], ah + mi * 4, bh0, bh1);
                    mma_bf16(acc[mi][bg * 2 + 0], ah + mi * 4, bl0, bl1);
                    mma_bf16(acc[mi][bg * 2 + 0], al + mi * 4, bh0, bh1);
                    mma_bf16(acc[mi][bg * 2 + 1], ah + mi * 4, bh2, bh3);
                    mma_bf16(acc[mi][bg * 2 + 1], ah + mi * 4, bl2, bl3);
                    mma_bf16(acc[mi][bg * 2 + 1], al + mi * 4, bh2, bh3);
                }
            }
        }
        __syncthreads();
    }

    // epilogue
    const int rbase = row0 + wm + (lane >> 2);
    const int cbase = wn + (lane & 3) * 2;
#pragma unroll
    for (int mi = 0; mi < 2; mi++) {
#pragma unroll
        for (int ni = 0; ni < 8; ni++) {
            int col = cbase + ni * 8;
            float b0 = __ldg(bias + col), b1 = __ldg(bias + col + 1);
            int r1 = rbase + mi * 16, r2 = r1 + 8;
            float v0 = acc[mi][ni][0] + b0, v1 = acc[mi][ni][1] + b1;
            float v2 = acc[mi][ni][2] + b0, v3 = acc[mi][ni][3] + b1;
            if (do_relu) {
                v0 = fmaxf(v0, 0.f); v1 = fmaxf(v1, 0.f);
                v2 = fmaxf(v2, 0.f); v3 = fmaxf(v3, 0.f);
            }
            if (r1 < M) *(float2*)(out + (size_t)r1 * CC + col) = make_float2(v0, v1);
            if (r2 < M) *(float2*)(out + (size_t)r2 * CC + col) = make_float2(v2, v3);
        }
    }
}

// ---------------------------------------------------------------------------
extern "C" void kernel_launch(void* const* d_in, const int* in_sizes, int n_in,
                              void* d_out, int out_size) {
    const float* x     = (const float*)d_in[0];
    const int*   ei    = (const int*)d_in[1];     // int32 (JAX canonicalizes int64->int32)
    const float* W1_l  = (const float*)d_in[2];
    const float* b1_l  = (const float*)d_in[3];
    const float* W1_r  = (const float*)d_in[4];
    const float* W2_l  = (const float*)d_in[5];
    const float* b2_l  = (const float*)d_in[6];
    const float* W2_r  = (const float*)d_in[7];
    const float* W_lin = (const float*)d_in[8];
    const float* b_lin = (const float*)d_in[9];
    float* out = (float*)d_out;

    const int M = in_sizes[0] / CC;      // 50000
    const int E = in_sizes[1] / 2;       // 600000

    float *agg, *cnt, *x1, *x2;
    __nv_bfloat16 *wbh, *wbl;
    cudaGetSymbolAddress((void**)&agg, g_agg);
    cudaGetSymbolAddress((void**)&cnt, g_cnt);
    cudaGetSymbolAddress((void**)&x1, g_x1);
    cudaGetSymbolAddress((void**)&x2, g_x2);
    cudaGetSymbolAddress((void**)&wbh, g_wbh);
    cudaGetSymbolAddress((void**)&wbl, g_wbl);

    const int TB = 256;
    const int gemmBlocks = (M + 127) / 128;
    const int scatterBlocks = 592;       // 4 CTAs/SM, ~4 batches of 32 edges per warp

    // weight prep (replayed every launch; deterministic)
    prep_w_kernel<<<384, TB>>>(W1_l, W1_r, W2_l, W2_r, W_lin, W_lin + 128 * CC, wbh, wbl);

    // layer 1 (scatter also accumulates in-degree into cnt)
    cudaMemsetAsync(cnt, 0, (size_t)M * sizeof(float));
    cudaMemsetAsync(agg, 0, (size_t)M * CC * sizeof(float));
    scatter_kernel<<<scatterBlocks, TB>>>(x, ei, agg, cnt, E);
    gemm_mma_kernel<<<gemmBlocks, TB>>>(agg, x, cnt, wbh, wbl, b1_l, x1, M, 1);

    // layer 2
    cudaMemsetAsync(agg, 0, (size_t)M * CC * sizeof(float));
    scatter_kernel<<<scatterBlocks, TB>>>(x1, ei, agg, nullptr, E);
    gemm_mma_kernel<<<gemmBlocks, TB>>>(agg, x1, cnt,
                                        wbh + 32768, wbl + 32768, b2_l, x2, M, 1);

    // final linear: [x1 | x2] @ W_lin + b_lin (no relu, no scaling)
    gemm_mma_kernel<<<gemmBlocks, TB>>>(x1, x2, nullptr,
                                        wbh + 65536, wbl + 65536, b_lin, out, M, 0);
}

// round 6
// speedup vs baseline: 4.1726x; 1.3927x over previous
#include <cuda_runtime.h>
#include <cuda_bf16.h>
#include <cstdint>

#define NN 50000
#define CC 128
#define EE 600000
#define NBLK_SCAN 98            // ceil(50000/512)

// Scratch (device globals; no cudaMalloc allowed)
__device__ float g_agg[NN * CC];
__device__ float g_x1[NN * CC];
__device__ float g_x2[NN * CC];
__device__ int   g_cnt[NN];
__device__ int   g_rs[NN];      // row starts (exclusive prefix of cnt)
__device__ int   g_cur[NN];     // fill cursors
__device__ int   g_csr[EE];     // neighbor (src) ids grouped by dst
__device__ int   g_part[128];
// Pre-transposed bf16 hi/lo weights: [gemm(3)][n(128)][k(256)]
__device__ __nv_bfloat16 g_wbh[3 * 128 * 256];
__device__ __nv_bfloat16 g_wbl[3 * 128 * 256];

// ---------------------------------------------------------------------------
__device__ __forceinline__ uint32_t smem_u32(const void* p) {
    uint32_t a;
    asm("{ .reg .u64 t; cvta.to.shared.u64 t, %1; cvt.u32.u64 %0, t; }" : "=r"(a) : "l"(p));
    return a;
}
__device__ __forceinline__ void ldsm_x4(uint32_t& r0, uint32_t& r1, uint32_t& r2, uint32_t& r3,
                                        uint32_t addr) {
    asm volatile("ldmatrix.sync.aligned.m8n8.x4.shared.b16 {%0,%1,%2,%3}, [%4];"
                 : "=r"(r0), "=r"(r1), "=r"(r2), "=r"(r3) : "r"(addr));
}
__device__ __forceinline__ void mma_bf16(float* d, const uint32_t* a, uint32_t b0, uint32_t b1) {
    asm volatile(
        "mma.sync.aligned.m16n8k16.row.col.f32.bf16.bf16.f32 "
        "{%0,%1,%2,%3}, {%4,%5,%6,%7}, {%8,%9}, {%0,%1,%2,%3};"
        : "+f"(d[0]), "+f"(d[1]), "+f"(d[2]), "+f"(d[3])
        : "r"(a[0]), "r"(a[1]), "r"(a[2]), "r"(a[3]), "r"(b0), "r"(b1));
}
__device__ __forceinline__ void cp_async16(uint32_t dst, const void* src) {
    asm volatile("cp.async.cg.shared.global [%0], [%1], 16;" :: "r"(dst), "l"(src) : "memory");
}

// ---------------------------------------------------------------------------
// CSR build
__global__ void count_kernel(const int* __restrict__ ei, int* __restrict__ cnt, int E) {
    int i = blockIdx.x * blockDim.x + threadIdx.x;
    int stride = gridDim.x * blockDim.x;
    for (; i < E; i += stride) atomicAdd(&cnt[ei[E + i]], 1);
}

__global__ void scan_local_kernel(const int* __restrict__ cnt, int* __restrict__ rs,
                                  int* __restrict__ part, int n) {
    __shared__ int sh[512];
    int t = threadIdx.x;
    int i = blockIdx.x * 512 + t;
    int v = (i < n) ? cnt[i] : 0;
    sh[t] = v;
    __syncthreads();
#pragma unroll
    for (int off = 1; off < 512; off <<= 1) {
        int add = (t >= off) ? sh[t - off] : 0;
        __syncthreads();
        sh[t] += add;
        __syncthreads();
    }
    if (i < n) rs[i] = sh[t] - v;
    if (t == 511) part[blockIdx.x] = sh[511];
}

__global__ void scan_part_kernel(int* __restrict__ part, int nb) {
    __shared__ int sh[128];
    int t = threadIdx.x;
    int v = (t < nb) ? part[t] : 0;
    sh[t] = v;
    __syncthreads();
#pragma unroll
    for (int off = 1; off < 128; off <<= 1) {
        int add = (t >= off) ? sh[t - off] : 0;
        __syncthreads();
        sh[t] += add;
        __syncthreads();
    }
    if (t < nb) part[t] = sh[t] - v;
}

__global__ void scan_add_kernel(int* __restrict__ rs, const int* __restrict__ part,
                                int* __restrict__ cur, int n) {
    int i = blockIdx.x * 512 + threadIdx.x;
    if (i < n) {
        int v = rs[i] + part[blockIdx.x];
        rs[i] = v;
        cur[i] = v;
    }
}

__global__ void fill_kernel(const int* __restrict__ ei, int* __restrict__ cur,
                            int* __restrict__ csr, int E) {
    int i = blockIdx.x * blockDim.x + threadIdx.x;
    int stride = gridDim.x * blockDim.x;
    for (; i < E; i += stride) {
        int slot = atomicAdd(&cur[ei[E + i]], 1);
        csr[slot] = ei[i];
    }
}

// ---------------------------------------------------------------------------
// gather-based mean aggregation: one warp per dst node, lane owns 4 floats.
__global__ __launch_bounds__(256) void gather_mean_kernel(
    const float* __restrict__ x, const int* __restrict__ csr,
    const int* __restrict__ rs, const int* __restrict__ cnt,
    float* __restrict__ out, int N) {
    int w = (blockIdx.x * blockDim.x + threadIdx.x) >> 5;
    if (w >= N) return;
    const int lane = threadIdx.x & 31;
    const int start = rs[w];
    const int deg = cnt[w];
    const int* nb = csr + start;

    float4 acc = make_float4(0.f, 0.f, 0.f, 0.f);
    int j = 0;
    for (; j + 4 <= deg; j += 4) {
        int s0 = __ldg(nb + j), s1 = __ldg(nb + j + 1);
        int s2 = __ldg(nb + j + 2), s3 = __ldg(nb + j + 3);
        float4 v0 = __ldg((const float4*)(x + (size_t)s0 * CC) + lane);
        float4 v1 = __ldg((const float4*)(x + (size_t)s1 * CC) + lane);
        float4 v2 = __ldg((const float4*)(x + (size_t)s2 * CC) + lane);
        float4 v3 = __ldg((const float4*)(x + (size_t)s3 * CC) + lane);
        acc.x += v0.x + v1.x + v2.x + v3.x;
        acc.y += v0.y + v1.y + v2.y + v3.y;
        acc.z += v0.z + v1.z + v2.z + v3.z;
        acc.w += v0.w + v1.w + v2.w + v3.w;
    }
    for (; j < deg; j++) {
        int s0 = __ldg(nb + j);
        float4 v0 = __ldg((const float4*)(x + (size_t)s0 * CC) + lane);
        acc.x += v0.x; acc.y += v0.y; acc.z += v0.z; acc.w += v0.w;
    }
    float inv = 1.0f / (float)(deg > 0 ? deg : 1);
    ((float4*)(out + (size_t)w * CC))[lane] =
        make_float4(acc.x * inv, acc.y * inv, acc.z * inv, acc.w * inv);
}

// ---------------------------------------------------------------------------
// Weight prep: W[k][n] (row-major, 2x 128x128 stacked in k) -> Wt[n][k] bf16 hi/lo
__global__ void prep_w_kernel(const float* w0l, const float* w0r,
                              const float* w1l, const float* w1r,
                              const float* w2l, const float* w2r,
                              __nv_bfloat16* wh, __nv_bfloat16* wl) {
    int gid = blockIdx.x * blockDim.x + threadIdx.x;   // [g][n][k]
    if (gid >= 3 * 128 * 256) return;
    int g = gid >> 15;
    int rem = gid & 32767;
    int n = rem >> 8;
    int k = rem & 255;
    const float* W;
    if (g == 0)      W = (k < 128) ? w0l : w0r;
    else if (g == 1) W = (k < 128) ? w1l : w1r;
    else             W = (k < 128) ? w2l : w2r;
    float v = W[(size_t)(k & 127) * CC + n];
    __nv_bfloat16 h = __float2bfloat16(v);
    __nv_bfloat16 l = __float2bfloat16(v - __bfloat162float(h));
    wh[gid] = h;
    wl[gid] = l;
}

// ---------------------------------------------------------------------------
// bf16x3 tensor-core GEMM via mma.sync, software-pipelined.
// out[M,128] = act( [A0 | A1] (Mx256) @ Wt^T + bias )
#define ROW_B 80

__global__ __launch_bounds__(256, 2) void gemm_mma_kernel(
    const float* __restrict__ A0, const float* __restrict__ A1,
    const __nv_bfloat16* __restrict__ wh, const __nv_bfloat16* __restrict__ wl,
    const float* __restrict__ bias,
    float* __restrict__ out, int M, int do_relu) {

    __shared__ __align__(16) char sA_hi[128 * ROW_B];
    __shared__ __align__(16) char sA_lo[128 * ROW_B];
    __shared__ __align__(16) char sB_hi[128 * ROW_B];
    __shared__ __align__(16) char sB_lo[128 * ROW_B];

    const int tid = threadIdx.x;
    const int lane = tid & 31;
    const int wid = tid >> 5;
    const int wm = (wid & 3) * 32;
    const int wn = (wid >> 2) * 64;
    const int row0 = blockIdx.x * 128;

    float acc[2][8][4] = {};

    const uint32_t aHi = smem_u32(sA_hi), aLo = smem_u32(sA_lo);
    const uint32_t bHi = smem_u32(sB_hi), bLo = smem_u32(sB_lo);

    const int a_mrow = ((lane >> 3) & 1) * 8 + (lane & 7);
    const int a_j = lane >> 4;
    const int b_nrow = (lane >> 4) * 8 + (lane & 7);
    const int b_j = (lane >> 3) & 1;

    float4 vA[4];

    auto loadA = [&](int c) {
        const float* SA = (c < 4) ? A0 : A1;
        const int koff = (c & 3) * 32;
#pragma unroll
        for (int i = 0; i < 4; i++) {
            int idx = tid + (i << 8);
            int m = idx >> 3, k4 = idx & 7;
            int row = row0 + m;
            vA[i] = (row < M) ? *(const float4*)(SA + (size_t)row * CC + koff + (k4 << 2))
                              : make_float4(0.f, 0.f, 0.f, 0.f);
        }
    };

    loadA(0);

    for (int c = 0; c < 8; c++) {
#pragma unroll
        for (int i = 0; i < 2; i++) {
            int idx = tid + (i << 8);
            int n = idx >> 2, j = idx & 3;
            size_t srcOff = (size_t)n * 512 + (size_t)c * 64 + (size_t)j * 16;
            cp_async16(bHi + n * ROW_B + (j << 4), (const char*)wh + srcOff);
            cp_async16(bLo + n * ROW_B + (j << 4), (const char*)wl + srcOff);
        }
        asm volatile("cp.async.commit_group;" ::: "memory");

#pragma unroll
        for (int i = 0; i < 4; i++) {
            int idx = tid + (i << 8);
            int m = idx >> 3, k4 = idx & 7;
            float x0 = vA[i].x, x1 = vA[i].y, x2 = vA[i].z, x3 = vA[i].w;
            __nv_bfloat162 h01 = make_bfloat162(__float2bfloat16(x0), __float2bfloat16(x1));
            __nv_bfloat162 h23 = make_bfloat162(__float2bfloat16(x2), __float2bfloat16(x3));
            __nv_bfloat162 l01 = make_bfloat162(
                __float2bfloat16(x0 - __bfloat162float(h01.x)),
                __float2bfloat16(x1 - __bfloat162float(h01.y)));
            __nv_bfloat162 l23 = make_bfloat162(
                __float2bfloat16(x2 - __bfloat162float(h23.x)),
                __float2bfloat16(x3 - __bfloat162float(h23.y)));
            char* pd = sA_hi + m * ROW_B + (k4 << 3);
            *(__nv_bfloat162*)(pd + 0) = h01;
            *(__nv_bfloat162*)(pd + 4) = h23;
            char* pl = sA_lo + m * ROW_B + (k4 << 3);
            *(__nv_bfloat162*)(pl + 0) = l01;
            *(__nv_bfloat162*)(pl + 4) = l23;
        }

        if (c < 7) loadA(c + 1);

        asm volatile("cp.async.wait_group 0;" ::: "memory");
        __syncthreads();

#pragma unroll
        for (int ks = 0; ks < 2; ks++) {
            uint32_t ah[8], al[8];
#pragma unroll
            for (int mi = 0; mi < 2; mi++) {
                uint32_t off = (uint32_t)((wm + mi * 16 + a_mrow) * ROW_B + ks * 32 + a_j * 16);
                ldsm_x4(ah[mi * 4 + 0], ah[mi * 4 + 1], ah[mi * 4 + 2], ah[mi * 4 + 3], aHi + off);
                ldsm_x4(al[mi * 4 + 0], al[mi * 4 + 1], al[mi * 4 + 2], al[mi * 4 + 3], aLo + off);
            }
#pragma unroll
            for (int bg = 0; bg < 4; bg++) {
                uint32_t off = (uint32_t)((wn + bg * 16 + b_nrow) * ROW_B + ks * 32 + b_j * 16);
                uint32_t bh0, bh1, bh2, bh3, bl0, bl1, bl2, bl3;
                ldsm_x4(bh0, bh1, bh2, bh3, bHi + off);
                ldsm_x4(bl0, bl1, bl2, bl3, bLo + off);
#pragma unroll
                for (int mi = 0; mi < 2; mi++) {
                    mma_bf16(acc[mi][bg * 2 + 0], ah + mi * 4, bh0, bh1);
                    mma_bf16(acc[mi][bg * 2 + 0], ah + mi * 4, bl0, bl1);
                    mma_bf16(acc[mi][bg * 2 + 0], al + mi * 4, bh0, bh1);
                    mma_bf16(acc[mi][bg * 2 + 1], ah + mi * 4, bh2, bh3);
                    mma_bf16(acc[mi][bg * 2 + 1], ah + mi * 4, bl2, bl3);
                    mma_bf16(acc[mi][bg * 2 + 1], al + mi * 4, bh2, bh3);
                }
            }
        }
        __syncthreads();
    }

    const int rbase = row0 + wm + (lane >> 2);
    const int cbase = wn + (lane & 3) * 2;
#pragma unroll
    for (int mi = 0; mi < 2; mi++) {
#pragma unroll
        for (int ni = 0; ni < 8; ni++) {
            int col = cbase + ni * 8;
            float b0 = __ldg(bias + col), b1 = __ldg(bias + col + 1);
            int r1 = rbase + mi * 16, r2 = r1 + 8;
            float v0 = acc[mi][ni][0] + b0, v1 = acc[mi][ni][1] + b1;
            float v2 = acc[mi][ni][2] + b0, v3 = acc[mi][ni][3] + b1;
            if (do_relu) {
                v0 = fmaxf(v0, 0.f); v1 = fmaxf(v1, 0.f);
                v2 = fmaxf(v2, 0.f); v3 = fmaxf(v3, 0.f);
            }
            if (r1 < M) *(float2*)(out + (size_t)r1 * CC + col) = make_float2(v0, v1);
            if (r2 < M) *(float2*)(out + (size_t)r2 * CC + col) = make_float2(v2, v3);
        }
    }
}

// ---------------------------------------------------------------------------
extern "C" void kernel_launch(void* const* d_in, const int* in_sizes, int n_in,
                              void* d_out, int out_size) {
    const float* x     = (const float*)d_in[0];
    const int*   ei    = (const int*)d_in[1];     // int32
    const float* W1_l  = (const float*)d_in[2];
    const float* b1_l  = (const float*)d_in[3];
    const float* W1_r  = (const float*)d_in[4];
    const float* W2_l  = (const float*)d_in[5];
    const float* b2_l  = (const float*)d_in[6];
    const float* W2_r  = (const float*)d_in[7];
    const float* W_lin = (const float*)d_in[8];
    const float* b_lin = (const float*)d_in[9];
    float* out = (float*)d_out;

    const int M = in_sizes[0] / CC;      // 50000
    const int E = in_sizes[1] / 2;       // 600000

    float *agg, *x1, *x2;
    int *cnt, *rs, *cur, *csr, *part;
    __nv_bfloat16 *wbh, *wbl;
    cudaGetSymbolAddress((void**)&agg, g_agg);
    cudaGetSymbolAddress((void**)&x1, g_x1);
    cudaGetSymbolAddress((void**)&x2, g_x2);
    cudaGetSymbolAddress((void**)&cnt, g_cnt);
    cudaGetSymbolAddress((void**)&rs, g_rs);
    cudaGetSymbolAddress((void**)&cur, g_cur);
    cudaGetSymbolAddress((void**)&csr, g_csr);
    cudaGetSymbolAddress((void**)&part, g_part);
    cudaGetSymbolAddress((void**)&wbh, g_wbh);
    cudaGetSymbolAddress((void**)&wbl, g_wbl);

    const int TB = 256;
    const int gemmBlocks = (M + 127) / 128;
    const int nScanBlk = (M + 511) / 512;
    const int gatherBlocks = (M * 32 + TB - 1) / TB;

    // weight prep
    prep_w_kernel<<<384, TB>>>(W1_l, W1_r, W2_l, W2_r, W_lin, W_lin + 128 * CC, wbh, wbl);

    // CSR build (shared by both layers)
    cudaMemsetAsync(cnt, 0, (size_t)M * sizeof(int));
    count_kernel<<<512, TB>>>(ei, cnt, E);
    scan_local_kernel<<<nScanBlk, 512>>>(cnt, rs, part, M);
    scan_part_kernel<<<1, 128>>>(part, nScanBlk);
    scan_add_kernel<<<nScanBlk, 512>>>(rs, part, cur, M);
    fill_kernel<<<512, TB>>>(ei, cur, csr, E);

    // layer 1
    gather_mean_kernel<<<gatherBlocks, TB>>>(x, csr, rs, cnt, agg, M);
    gemm_mma_kernel<<<gemmBlocks, TB>>>(agg, x, wbh, wbl, b1_l, x1, M, 1);

    // layer 2
    gather_mean_kernel<<<gatherBlocks, TB>>>(x1, csr, rs, cnt, agg, M);
    gemm_mma_kernel<<<gemmBlocks, TB>>>(agg, x1, wbh + 32768, wbl + 32768, b2_l, x2, M, 1);

    // final linear: [x1 | x2] @ W_lin + b_lin (no relu)
    gemm_mma_kernel<<<gemmBlocks, TB>>>(x1, x2, wbh + 65536, wbl + 65536, b_lin, out, M, 0);
}